// round 3
// baseline (speedup 1.0000x reference)
#include <cuda_runtime.h>
#include <cuda_bf16.h>
#include <math_constants.h>

// Problem constants
#define NQ   65536          // 16*4096 query vectors
#define DIM  64
#define NK   8192           // codebook size
#define TQ   128            // queries per block (argmin kernel)
#define TK   128            // codes per k-tile

// Output layout (flattened fp32, reference return order)
#define ZQ_OFF   0
#define LOSS_OFF 4194304
#define ENC_OFF  4194305
#define CS_OFF   4259841
#define EA_OFF   4268033
#define W_OFF    4792321

typedef unsigned long long ull;

// ------------------------- scratch (device globals; no allocs) ------------
__device__ float  g_zn[(size_t)NQ * DIM];     // normalized z (16 MB)
__device__ float  g_w2[NK];                   // per-code squared norm
__device__ int    g_enc[NQ];                  // argmin indices
__device__ float  g_bins[NK];                 // histogram
__device__ float  g_es[(size_t)NK * DIM];     // embed_sum (2 MB)
__device__ double g_loss;                     // loss accumulator

// ------------------------- f32x2 helpers ----------------------------------
__device__ __forceinline__ void fma2(ull& d, ull a, ull b) {
    asm("fma.rn.f32x2 %0, %1, %2, %0;" : "+l"(d) : "l"(a), "l"(b));
}
__device__ __forceinline__ void unpack2(ull v, float& lo, float& hi) {
    asm("mov.b64 {%0, %1}, %2;" : "=f"(lo), "=f"(hi) : "l"(v));
}

// ------------------------- kernel 0: zero scratch --------------------------
__global__ void k_zero() {
    int idx = blockIdx.x * blockDim.x + threadIdx.x;
    if (idx < NK * DIM) g_es[idx] = 0.0f;
    int j = idx - NK * DIM;
    if (j >= 0 && j < NK) g_bins[j] = 0.0f;
    if (idx == 0) g_loss = 0.0;
}

// ------------------------- kernel 1: normalize z ---------------------------
__global__ void k_normz(const float* __restrict__ Z) {
    int warp = (blockIdx.x * blockDim.x + threadIdx.x) >> 5;
    int lane = threadIdx.x & 31;
    if (warp >= NQ) return;
    float2 v = reinterpret_cast<const float2*>(Z)[(size_t)warp * 32 + lane];
    float ss = v.x * v.x + v.y * v.y;
    #pragma unroll
    for (int off = 16; off > 0; off >>= 1)
        ss += __shfl_xor_sync(0xffffffffu, ss, off);
    float inv = 1.0f / fmaxf(sqrtf(ss), 1e-12f);
    reinterpret_cast<float2*>(g_zn)[(size_t)warp * 32 + lane] =
        make_float2(v.x * inv, v.y * inv);
}

// ------------------------- kernel 2: w2 ------------------------------------
__global__ void k_w2(const float* __restrict__ W) {
    int warp = (blockIdx.x * blockDim.x + threadIdx.x) >> 5;
    int lane = threadIdx.x & 31;
    if (warp >= NK) return;
    float2 v = reinterpret_cast<const float2*>(W)[(size_t)warp * 32 + lane];
    float ss = v.x * v.x + v.y * v.y;
    #pragma unroll
    for (int off = 16; off > 0; off >>= 1)
        ss += __shfl_xor_sync(0xffffffffu, ss, off);
    if (lane == 0) g_w2[warp] = ss;
}

// ------------------------- kernel 3: argmin (f32x2 SGEMM-argmin) -----------
// Block: 256 threads = 16(tx over k) x 16(ty over q). Micro-tile 8q x 8k.
// Z kept PACKED as q-pairs: sZn[d][q] = zn[q][d]  (ull view = (q_even,q_odd))
//                           sZs[d][q] = zn[q^1][d] (swapped pairs)
// 2q x 2k outer product = 2 FFMA2: diag (a) + anti-diag (a_swapped).
// k mapping per thread: pair ki covers codes ki*32 + tx*2 + {0,1}
//  -> each B LDS.64 reads 128 contiguous bytes across the 16 tx lanes (1 wf).
__global__ __launch_bounds__(256, 2)
void k_argmin(const float* __restrict__ W) {
    extern __shared__ float sm[];
    float* sZn = sm;                       // 64*128 floats, packed q-pairs
    float* sZs = sm + 64 * 128;            // 64*128 floats, swapped q-pairs
    float* sW  = sm + 2 * 64 * 128;        // 64*128 floats, packed k-pairs
    float* sw2 = sW + 64 * 128;            // 128 floats

    const int tid = threadIdx.x;
    const int tx = tid & 15;
    const int ty = tid >> 4;
    const int q0 = blockIdx.x * TQ;

    // Load Z tile transposed: sZn[d][q] = zn[q][d], sZs[d][q^1] = zn[q][d]
    {
        const float4* Z4 = reinterpret_cast<const float4*>(g_zn) + (size_t)q0 * 16;
        #pragma unroll
        for (int rep = 0; rep < 8; ++rep) {
            int idx = rep * 256 + tid;
            int c4 = idx >> 7, q = idx & 127;
            float4 v = Z4[(size_t)q * 16 + c4];
            int qx = q ^ 1;
            sZn[(c4 * 4 + 0) * 128 + q] = v.x;  sZs[(c4 * 4 + 0) * 128 + qx] = v.x;
            sZn[(c4 * 4 + 1) * 128 + q] = v.y;  sZs[(c4 * 4 + 1) * 128 + qx] = v.y;
            sZn[(c4 * 4 + 2) * 128 + q] = v.z;  sZs[(c4 * 4 + 2) * 128 + qx] = v.z;
            sZn[(c4 * 4 + 3) * 128 + q] = v.w;  sZs[(c4 * 4 + 3) * 128 + qx] = v.w;
        }
    }

    // local q slot r = qi*2 + parity  ->  global q = q0 + ty*8 + r
    float minv[8];
    int   mini[8];
    #pragma unroll
    for (int i = 0; i < 8; ++i) { minv[i] = CUDART_INF_F; mini[i] = 0; }

    for (int kt = 0; kt < NK / TK; ++kt) {
        __syncthreads();  // previous tile compute done (and sZ visible on kt==0)
        // Load W tile transposed: sW[d][k] = W[kt*128+k][d]
        {
            const float4* W4 = reinterpret_cast<const float4*>(W) + (size_t)kt * TK * 16;
            #pragma unroll
            for (int rep = 0; rep < 8; ++rep) {
                int idx = rep * 256 + tid;
                int c4 = idx >> 7, k = idx & 127;
                float4 v = W4[(size_t)k * 16 + c4];
                sW[(c4 * 4 + 0) * 128 + k] = v.x;
                sW[(c4 * 4 + 1) * 128 + k] = v.y;
                sW[(c4 * 4 + 2) * 128 + k] = v.z;
                sW[(c4 * 4 + 3) * 128 + k] = v.w;
            }
            if (tid < 128) sw2[tid] = g_w2[kt * 128 + tid];
        }
        __syncthreads();

        ull accD[16], accA[16];
        #pragma unroll
        for (int i = 0; i < 16; ++i) { accD[i] = 0ull; accA[i] = 0ull; }

        #pragma unroll 8
        for (int d = 0; d < 64; ++d) {
            const ull* bp = reinterpret_cast<const ull*>(&sW[d * 128]);
            ull b0 = bp[0 * 16 + tx];
            ull b1 = bp[1 * 16 + tx];
            ull b2 = bp[2 * 16 + tx];
            ull b3 = bp[3 * 16 + tx];
            const ulonglong2* an = reinterpret_cast<const ulonglong2*>(&sZn[d * 128]) + ty * 2;
            const ulonglong2* as = reinterpret_cast<const ulonglong2*>(&sZs[d * 128]) + ty * 2;
            ulonglong2 a01 = an[0], a23 = an[1];
            ulonglong2 s01 = as[0], s23 = as[1];

            #define QSTEP(qi, A, S)                      \
                fma2(accD[(qi)*4 + 0], (A), b0);         \
                fma2(accA[(qi)*4 + 0], (S), b0);         \
                fma2(accD[(qi)*4 + 1], (A), b1);         \
                fma2(accA[(qi)*4 + 1], (S), b1);         \
                fma2(accD[(qi)*4 + 2], (A), b2);         \
                fma2(accA[(qi)*4 + 2], (S), b2);         \
                fma2(accD[(qi)*4 + 3], (A), b3);         \
                fma2(accA[(qi)*4 + 3], (S), b3);
            QSTEP(0, a01.x, s01.x)
            QSTEP(1, a01.y, s01.y)
            QSTEP(2, a23.x, s23.x)
            QSTEP(3, a23.y, s23.y)
            #undef QSTEP
        }

        // epilogue. accD = (qe*ke, qo*ko), accA = (qo*ke, qe*ko).
        // ki ascending + ke before ko => ascending k; strict < keeps lowest idx.
        #pragma unroll
        for (int qi = 0; qi < 4; ++qi) {
            #pragma unroll
            for (int ki = 0; ki < 4; ++ki) {
                float de, dh, ae, ah;
                unpack2(accD[qi * 4 + ki], de, dh);
                unpack2(accA[qi * 4 + ki], ae, ah);
                float w2e = sw2[ki * 32 + tx * 2];
                float w2o = sw2[ki * 32 + tx * 2 + 1];
                int ke = kt * 128 + ki * 32 + tx * 2;
                // q_even (slot qi*2)
                float se0 = fmaf(-2.0f, de, w2e);
                float se1 = fmaf(-2.0f, ah, w2o);
                if (se0 < minv[qi * 2]) { minv[qi * 2] = se0; mini[qi * 2] = ke; }
                if (se1 < minv[qi * 2]) { minv[qi * 2] = se1; mini[qi * 2] = ke + 1; }
                // q_odd (slot qi*2+1)
                float so0 = fmaf(-2.0f, ae, w2e);
                float so1 = fmaf(-2.0f, dh, w2o);
                if (so0 < minv[qi * 2 + 1]) { minv[qi * 2 + 1] = so0; mini[qi * 2 + 1] = ke; }
                if (so1 < minv[qi * 2 + 1]) { minv[qi * 2 + 1] = so1; mini[qi * 2 + 1] = ke + 1; }
            }
        }
    }

    // reduce across the 16 tx-threads (same half-warp, width 16)
    #pragma unroll
    for (int off = 8; off > 0; off >>= 1) {
        #pragma unroll
        for (int r = 0; r < 8; ++r) {
            float ov = __shfl_down_sync(0xffffffffu, minv[r], off, 16);
            int   oi = __shfl_down_sync(0xffffffffu, mini[r], off, 16);
            if (ov < minv[r] || (ov == minv[r] && oi < mini[r])) {
                minv[r] = ov; mini[r] = oi;
            }
        }
    }
    if (tx == 0) {
        #pragma unroll
        for (int r = 0; r < 8; ++r)
            g_enc[q0 + ty * 8 + r] = mini[r];
    }
}

// ------------------------- kernel 4: scatter / z_q / loss ------------------
__global__ void k_scatter(const float* __restrict__ W, float* __restrict__ out) {
    int warp = (blockIdx.x * blockDim.x + threadIdx.x) >> 5;
    int lane = threadIdx.x & 31;
    if (warp >= NQ) return;
    int e = g_enc[warp];

    float2 wv = reinterpret_cast<const float2*>(W)[(size_t)e * 32 + lane];
    float2 zv = reinterpret_cast<const float2*>(g_zn)[(size_t)warp * 32 + lane];
    float d0 = wv.x - zv.x, d1 = wv.y - zv.y;
    reinterpret_cast<float2*>(out + ZQ_OFF)[(size_t)warp * 32 + lane] =
        make_float2(zv.x + d0, zv.y + d1);

    atomicAdd(&g_es[(size_t)e * 64 + 2 * lane],     zv.x);
    atomicAdd(&g_es[(size_t)e * 64 + 2 * lane + 1], zv.y);

    float part = d0 * d0 + d1 * d1;
    #pragma unroll
    for (int off = 16; off > 0; off >>= 1)
        part += __shfl_xor_sync(0xffffffffu, part, off);
    if (lane == 0) {
        atomicAdd(&g_bins[e], 1.0f);
        atomicAdd(&g_loss, (double)part);
        out[ENC_OFF + warp] = (float)e;
    }
}

// ------------------------- kernel 5: per-code EMA updates ------------------
__global__ void k_update(const float* __restrict__ W,
                         const float* __restrict__ CS,
                         const float* __restrict__ EA,
                         float* __restrict__ out) {
    int warp = (blockIdx.x * blockDim.x + threadIdx.x) >> 5;
    int lane = threadIdx.x & 31;
    if (blockIdx.x == 0 && threadIdx.x == 0) {
        out[LOSS_OFF] = (float)(0.25 * (g_loss / (double)((size_t)NQ * DIM)));
    }
    if (warp >= NK) return;
    int k = warp;

    float b = g_bins[k];
    float2 es = reinterpret_cast<const float2*>(g_es)[(size_t)k * 32 + lane];
    float2 ea = reinterpret_cast<const float2*>(EA)[(size_t)k * 32 + lane];

    out[EA_OFF + (size_t)k * 64 + 2 * lane]     = ea.x * 0.99f + 0.01f * es.x;
    out[EA_OFF + (size_t)k * 64 + 2 * lane + 1] = ea.y * 0.99f + 0.01f * es.y;

    float bc = (b == 0.0f) ? 1.0f : b;
    float vx = es.x / bc, vy = es.y / bc;
    float ss = vx * vx + vy * vy;
    #pragma unroll
    for (int off = 16; off > 0; off >>= 1)
        ss += __shfl_xor_sync(0xffffffffu, ss, off);
    float inv = 1.0f / fmaxf(sqrtf(ss), 1e-12f);

    float2 wv = reinterpret_cast<const float2*>(W)[(size_t)k * 32 + lane];
    float enx = (b == 0.0f) ? wv.x : vx * inv;
    float eny = (b == 0.0f) ? wv.y : vy * inv;

    float nwx = wv.x * 0.99f + 0.01f * enx;
    float nwy = wv.y * 0.99f + 0.01f * eny;
    float ss2 = nwx * nwx + nwy * nwy;
    #pragma unroll
    for (int off = 16; off > 0; off >>= 1)
        ss2 += __shfl_xor_sync(0xffffffffu, ss2, off);
    float inv2 = 1.0f / fmaxf(sqrtf(ss2), 1e-12f);

    out[W_OFF + (size_t)k * 64 + 2 * lane]     = nwx * inv2;
    out[W_OFF + (size_t)k * 64 + 2 * lane + 1] = nwy * inv2;

    if (lane == 0) out[CS_OFF + k] = CS[k] * 0.99f + 0.01f * b;
}

// ------------------------- launch -------------------------------------------
extern "C" void kernel_launch(void* const* d_in, const int* in_sizes, int n_in,
                              void* d_out, int out_size) {
    const float* z  = (const float*)d_in[0];
    const float* w  = (const float*)d_in[1];
    const float* cs = (const float*)d_in[2];
    const float* ea = (const float*)d_in[3];
    float* out = (float*)d_out;

    const int smem_bytes = (3 * 64 * 128 + 128) * sizeof(float);  // 98816
    cudaFuncSetAttribute(k_argmin, cudaFuncAttributeMaxDynamicSharedMemorySize,
                         smem_bytes);

    k_zero<<<(NK * DIM + NK + 255) / 256, 256>>>();
    k_normz<<<NQ / 8, 256>>>(z);
    k_w2<<<NK / 8, 256>>>(w);
    k_argmin<<<NQ / TQ, 256, smem_bytes>>>(w);
    k_scatter<<<NQ / 8, 256>>>(w, out);
    k_update<<<NK / 8, 256>>>(w, cs, ea, out);
}

// round 4
// speedup vs baseline: 1.5429x; 1.5429x over previous
#include <cuda_runtime.h>
#include <cuda_bf16.h>
#include <math_constants.h>

// Problem constants
#define NQ   65536          // 16*4096 query vectors
#define DIM  64
#define NK   8192           // codebook size
#define TQ   128            // queries per block (argmin kernel)
#define TK   128            // codes per k-tile

// Output layout (flattened fp32, reference return order)
#define ZQ_OFF   0
#define LOSS_OFF 4194304
#define ENC_OFF  4194305
#define CS_OFF   4259841
#define EA_OFF   4268033
#define W_OFF    4792321

typedef unsigned long long ull;

// ------------------------- scratch (device globals; no allocs) ------------
__device__ float  g_zn[(size_t)NQ * DIM];     // normalized z (16 MB)
__device__ float  g_w2[NK];                   // per-code squared norm
__device__ int    g_enc[NQ];                  // argmin indices
__device__ float  g_bins[NK];                 // histogram
__device__ float  g_es[(size_t)NK * DIM];     // embed_sum (2 MB)
__device__ double g_loss;                     // loss accumulator

// ------------------------- f32x2 helpers ----------------------------------
__device__ __forceinline__ void fma2(ull& d, ull a, ull b) {
    asm("fma.rn.f32x2 %0, %1, %2, %0;" : "+l"(d) : "l"(a), "l"(b));
}
__device__ __forceinline__ void unpack2(ull v, float& lo, float& hi) {
    asm("mov.b64 {%0, %1}, %2;" : "=f"(lo), "=f"(hi) : "l"(v));
}

// ------------------------- kernel 0: zero scratch --------------------------
__global__ void k_zero() {
    int idx = blockIdx.x * blockDim.x + threadIdx.x;
    if (idx < NK * DIM) g_es[idx] = 0.0f;
    int j = idx - NK * DIM;
    if (j >= 0 && j < NK) g_bins[j] = 0.0f;
    if (idx == 0) g_loss = 0.0;
}

// ------------------------- kernel 1: normalize z ---------------------------
__global__ void k_normz(const float* __restrict__ Z) {
    int warp = (blockIdx.x * blockDim.x + threadIdx.x) >> 5;
    int lane = threadIdx.x & 31;
    if (warp >= NQ) return;
    float2 v = reinterpret_cast<const float2*>(Z)[(size_t)warp * 32 + lane];
    float ss = v.x * v.x + v.y * v.y;
    #pragma unroll
    for (int off = 16; off > 0; off >>= 1)
        ss += __shfl_xor_sync(0xffffffffu, ss, off);
    float inv = 1.0f / fmaxf(sqrtf(ss), 1e-12f);
    reinterpret_cast<float2*>(g_zn)[(size_t)warp * 32 + lane] =
        make_float2(v.x * inv, v.y * inv);
}

// ------------------------- kernel 2: w2 ------------------------------------
__global__ void k_w2(const float* __restrict__ W) {
    int warp = (blockIdx.x * blockDim.x + threadIdx.x) >> 5;
    int lane = threadIdx.x & 31;
    if (warp >= NK) return;
    float2 v = reinterpret_cast<const float2*>(W)[(size_t)warp * 32 + lane];
    float ss = v.x * v.x + v.y * v.y;
    #pragma unroll
    for (int off = 16; off > 0; off >>= 1)
        ss += __shfl_xor_sync(0xffffffffu, ss, off);
    if (lane == 0) g_w2[warp] = ss;
}

// ------------------------- kernel 3: argmin (f32x2 SGEMM-argmin) -----------
// Block: 256 threads = 16(tx over k) x 16(ty over q). Micro-tile 8q x 8k.
// Z stored as duplicated pairs (round-2 layout): sZ[d] has 128 float2, each (z,z).
// B: thread's 8 codes are CONTIGUOUS: tx*8 + {0..7}  -> 2 x LDS.128 per d.
// A: 4 x LDS.128 per d (broadcast), loaded in two halves to limit live regs.
__global__ __launch_bounds__(256, 2)
void k_argmin(const float* __restrict__ W) {
    extern __shared__ float sm[];
    float* sZ  = sm;                      // 64 * 256 floats (duplicated pairs)
    float* sW  = sm + 64 * 256;           // 64 * 128 floats
    float* sw2 = sW + 64 * 128;           // 128 floats

    const int tid = threadIdx.x;
    const int tx = tid & 15;
    const int ty = tid >> 4;
    const int q0 = blockIdx.x * TQ;

    // Load Z tile, transposed + duplicated: sZ[d][2q]=sZ[d][2q+1]=zn[q][d]
    {
        const float4* Z4 = reinterpret_cast<const float4*>(g_zn) + (size_t)q0 * 16;
        float2* sZ2 = reinterpret_cast<float2*>(sZ);
        #pragma unroll
        for (int rep = 0; rep < 8; ++rep) {
            int idx = rep * 256 + tid;
            int c4 = idx >> 7, q = idx & 127;
            float4 v = Z4[(size_t)q * 16 + c4];
            sZ2[(c4 * 4 + 0) * 128 + q] = make_float2(v.x, v.x);
            sZ2[(c4 * 4 + 1) * 128 + q] = make_float2(v.y, v.y);
            sZ2[(c4 * 4 + 2) * 128 + q] = make_float2(v.z, v.z);
            sZ2[(c4 * 4 + 3) * 128 + q] = make_float2(v.w, v.w);
        }
    }

    float minv[8];
    int   mini[8];
    #pragma unroll
    for (int i = 0; i < 8; ++i) { minv[i] = CUDART_INF_F; mini[i] = 0; }

    for (int kt = 0; kt < NK / TK; ++kt) {
        __syncthreads();  // previous tile compute done (and sZ visible on kt==0)
        // Load W tile transposed: sW[d][k] = W[kt*128+k][d]
        {
            const float4* W4 = reinterpret_cast<const float4*>(W) + (size_t)kt * TK * 16;
            #pragma unroll
            for (int rep = 0; rep < 8; ++rep) {
                int idx = rep * 256 + tid;
                int c4 = idx >> 7, k = idx & 127;
                float4 v = W4[(size_t)k * 16 + c4];
                sW[(c4 * 4 + 0) * 128 + k] = v.x;
                sW[(c4 * 4 + 1) * 128 + k] = v.y;
                sW[(c4 * 4 + 2) * 128 + k] = v.z;
                sW[(c4 * 4 + 3) * 128 + k] = v.w;
            }
            if (tid < 128) sw2[tid] = g_w2[kt * 128 + tid];
        }
        __syncthreads();

        ull acc[32];
        #pragma unroll
        for (int i = 0; i < 32; ++i) acc[i] = 0ull;  // (0.f, 0.f)

        #pragma unroll 8
        for (int d = 0; d < 64; ++d) {
            // B: codes tx*8 + {0..7}, 32 contiguous bytes -> 2 x LDS.128
            const ulonglong2* bp =
                reinterpret_cast<const ulonglong2*>(&sW[d * 128]) + tx * 2;
            ulonglong2 b01 = bp[0];   // pairs (codes 0,1) (2,3)
            ulonglong2 b23 = bp[1];   // pairs (codes 4,5) (6,7)
            // A: duplicated pairs, 2 x LDS.128 per half (broadcast)
            const ulonglong2* ap =
                reinterpret_cast<const ulonglong2*>(sZ) + d * 64 + ty * 4;
            {
                ulonglong2 a01 = ap[0], a23 = ap[1];
                #define QS(qi, A)                       \
                    fma2(acc[(qi)*4 + 0], (A), b01.x);  \
                    fma2(acc[(qi)*4 + 1], (A), b01.y);  \
                    fma2(acc[(qi)*4 + 2], (A), b23.x);  \
                    fma2(acc[(qi)*4 + 3], (A), b23.y);
                QS(0, a01.x) QS(1, a01.y) QS(2, a23.x) QS(3, a23.y)
            }
            {
                ulonglong2 a45 = ap[2], a67 = ap[3];
                QS(4, a45.x) QS(5, a45.y) QS(6, a67.x) QS(7, a67.y)
                #undef QS
            }
        }

        // epilogue: score = w2[k] - 2*dot ; ascending scan keeps lowest index
        int kbase = kt * 128 + tx * 8;
        #pragma unroll
        for (int qi = 0; qi < 8; ++qi) {
            #pragma unroll
            for (int j = 0; j < 4; ++j) {
                float lo, hi;
                unpack2(acc[qi * 4 + j], lo, hi);
                float s0 = fmaf(-2.0f, lo, sw2[tx * 8 + 2 * j]);
                float s1 = fmaf(-2.0f, hi, sw2[tx * 8 + 2 * j + 1]);
                int k0 = kbase + 2 * j;
                if (s0 < minv[qi]) { minv[qi] = s0; mini[qi] = k0; }
                if (s1 < minv[qi]) { minv[qi] = s1; mini[qi] = k0 + 1; }
            }
        }
    }

    // reduce across the 16 tx-threads (same half-warp, width 16)
    #pragma unroll
    for (int off = 8; off > 0; off >>= 1) {
        #pragma unroll
        for (int qi = 0; qi < 8; ++qi) {
            float ov = __shfl_down_sync(0xffffffffu, minv[qi], off, 16);
            int   oi = __shfl_down_sync(0xffffffffu, mini[qi], off, 16);
            if (ov < minv[qi] || (ov == minv[qi] && oi < mini[qi])) {
                minv[qi] = ov; mini[qi] = oi;
            }
        }
    }
    if (tx == 0) {
        #pragma unroll
        for (int qi = 0; qi < 8; ++qi)
            g_enc[q0 + ty * 8 + qi] = mini[qi];
    }
}

// ------------------------- kernel 4: scatter / z_q / loss ------------------
__global__ void k_scatter(const float* __restrict__ W, float* __restrict__ out) {
    int warp = (blockIdx.x * blockDim.x + threadIdx.x) >> 5;
    int lane = threadIdx.x & 31;
    if (warp >= NQ) return;
    int e = g_enc[warp];

    float2 wv = reinterpret_cast<const float2*>(W)[(size_t)e * 32 + lane];
    float2 zv = reinterpret_cast<const float2*>(g_zn)[(size_t)warp * 32 + lane];
    float d0 = wv.x - zv.x, d1 = wv.y - zv.y;
    reinterpret_cast<float2*>(out + ZQ_OFF)[(size_t)warp * 32 + lane] =
        make_float2(zv.x + d0, zv.y + d1);

    atomicAdd(&g_es[(size_t)e * 64 + 2 * lane],     zv.x);
    atomicAdd(&g_es[(size_t)e * 64 + 2 * lane + 1], zv.y);

    float part = d0 * d0 + d1 * d1;
    #pragma unroll
    for (int off = 16; off > 0; off >>= 1)
        part += __shfl_xor_sync(0xffffffffu, part, off);
    if (lane == 0) {
        atomicAdd(&g_bins[e], 1.0f);
        atomicAdd(&g_loss, (double)part);
        out[ENC_OFF + warp] = (float)e;
    }
}

// ------------------------- kernel 5: per-code EMA updates ------------------
__global__ void k_update(const float* __restrict__ W,
                         const float* __restrict__ CS,
                         const float* __restrict__ EA,
                         float* __restrict__ out) {
    int warp = (blockIdx.x * blockDim.x + threadIdx.x) >> 5;
    int lane = threadIdx.x & 31;
    if (blockIdx.x == 0 && threadIdx.x == 0) {
        out[LOSS_OFF] = (float)(0.25 * (g_loss / (double)((size_t)NQ * DIM)));
    }
    if (warp >= NK) return;
    int k = warp;

    float b = g_bins[k];
    float2 es = reinterpret_cast<const float2*>(g_es)[(size_t)k * 32 + lane];
    float2 ea = reinterpret_cast<const float2*>(EA)[(size_t)k * 32 + lane];

    out[EA_OFF + (size_t)k * 64 + 2 * lane]     = ea.x * 0.99f + 0.01f * es.x;
    out[EA_OFF + (size_t)k * 64 + 2 * lane + 1] = ea.y * 0.99f + 0.01f * es.y;

    float bc = (b == 0.0f) ? 1.0f : b;
    float vx = es.x / bc, vy = es.y / bc;
    float ss = vx * vx + vy * vy;
    #pragma unroll
    for (int off = 16; off > 0; off >>= 1)
        ss += __shfl_xor_sync(0xffffffffu, ss, off);
    float inv = 1.0f / fmaxf(sqrtf(ss), 1e-12f);

    float2 wv = reinterpret_cast<const float2*>(W)[(size_t)k * 32 + lane];
    float enx = (b == 0.0f) ? wv.x : vx * inv;
    float eny = (b == 0.0f) ? wv.y : vy * inv;

    float nwx = wv.x * 0.99f + 0.01f * enx;
    float nwy = wv.y * 0.99f + 0.01f * eny;
    float ss2 = nwx * nwx + nwy * nwy;
    #pragma unroll
    for (int off = 16; off > 0; off >>= 1)
        ss2 += __shfl_xor_sync(0xffffffffu, ss2, off);
    float inv2 = 1.0f / fmaxf(sqrtf(ss2), 1e-12f);

    out[W_OFF + (size_t)k * 64 + 2 * lane]     = nwx * inv2;
    out[W_OFF + (size_t)k * 64 + 2 * lane + 1] = nwy * inv2;

    if (lane == 0) out[CS_OFF + k] = CS[k] * 0.99f + 0.01f * b;
}

// ------------------------- launch -------------------------------------------
extern "C" void kernel_launch(void* const* d_in, const int* in_sizes, int n_in,
                              void* d_out, int out_size) {
    const float* z  = (const float*)d_in[0];
    const float* w  = (const float*)d_in[1];
    const float* cs = (const float*)d_in[2];
    const float* ea = (const float*)d_in[3];
    float* out = (float*)d_out;

    const int smem_bytes = (64 * 256 + 64 * 128 + 128) * sizeof(float);  // 98816
    cudaFuncSetAttribute(k_argmin, cudaFuncAttributeMaxDynamicSharedMemorySize,
                         smem_bytes);

    k_zero<<<(NK * DIM + NK + 255) / 256, 256>>>();
    k_normz<<<NQ / 8, 256>>>(z);
    k_w2<<<NK / 8, 256>>>(w);
    k_argmin<<<NQ / TQ, 256, smem_bytes>>>(w);
    k_scatter<<<NQ / 8, 256>>>(w, out);
    k_update<<<NK / 8, 256>>>(w, cs, ea, out);
}

// round 5
// speedup vs baseline: 1.5617x; 1.0122x over previous
#include <cuda_runtime.h>
#include <cuda_bf16.h>
#include <math_constants.h>

// Problem constants
#define NQ   65536          // 16*4096 query vectors
#define DIM  64
#define NK   8192           // codebook size
#define TQ   128            // queries per block (argmin kernel)
#define TK   128            // codes per k-tile

// Output layout (flattened fp32, reference return order)
#define ZQ_OFF   0
#define LOSS_OFF 4194304
#define ENC_OFF  4194305
#define CS_OFF   4259841
#define EA_OFF   4268033
#define W_OFF    4792321

typedef unsigned long long ull;

// ------------------------- scratch (device globals; no allocs) ------------
__device__ float  g_zn[(size_t)NQ * DIM];     // normalized z (16 MB)
__device__ float  g_w2[NK];                   // per-code squared norm
__device__ int    g_enc[NQ];                  // argmin indices
__device__ float  g_bins[NK];                 // histogram
__device__ float  g_es[(size_t)NK * DIM];     // embed_sum (2 MB)
__device__ double g_loss;                     // loss accumulator

// ------------------------- f32x2 helpers ----------------------------------
__device__ __forceinline__ void fma2(ull& d, ull a, ull b) {
    asm("fma.rn.f32x2 %0, %1, %2, %0;" : "+l"(d) : "l"(a), "l"(b));
}
__device__ __forceinline__ void unpack2(ull v, float& lo, float& hi) {
    asm("mov.b64 {%0, %1}, %2;" : "=f"(lo), "=f"(hi) : "l"(v));
}
// swap halves of an f32x2 register pair; copies forced onto the ALU pipe (PRMT)
__device__ __forceinline__ ull swap2(ull a) {
    unsigned lo, hi, slo, shi;
    asm("mov.b64 {%0, %1}, %2;" : "=r"(lo), "=r"(hi) : "l"(a));
    asm("prmt.b32 %0, %1, %1, 0x3210;" : "=r"(slo) : "r"(hi));
    asm("prmt.b32 %0, %1, %1, 0x3210;" : "=r"(shi) : "r"(lo));
    ull r;
    asm("mov.b64 %0, {%1, %2};" : "=l"(r) : "r"(slo), "r"(shi));
    return r;
}

// ------------------------- kernel 0: zero scratch --------------------------
__global__ void k_zero() {
    int idx = blockIdx.x * blockDim.x + threadIdx.x;
    if (idx < NK * DIM) g_es[idx] = 0.0f;
    int j = idx - NK * DIM;
    if (j >= 0 && j < NK) g_bins[j] = 0.0f;
    if (idx == 0) g_loss = 0.0;
}

// ------------------------- kernel 1: normalize z ---------------------------
__global__ void k_normz(const float* __restrict__ Z) {
    int warp = (blockIdx.x * blockDim.x + threadIdx.x) >> 5;
    int lane = threadIdx.x & 31;
    if (warp >= NQ) return;
    float2 v = reinterpret_cast<const float2*>(Z)[(size_t)warp * 32 + lane];
    float ss = v.x * v.x + v.y * v.y;
    #pragma unroll
    for (int off = 16; off > 0; off >>= 1)
        ss += __shfl_xor_sync(0xffffffffu, ss, off);
    float inv = 1.0f / fmaxf(sqrtf(ss), 1e-12f);
    reinterpret_cast<float2*>(g_zn)[(size_t)warp * 32 + lane] =
        make_float2(v.x * inv, v.y * inv);
}

// ------------------------- kernel 2: w2 ------------------------------------
__global__ void k_w2(const float* __restrict__ W) {
    int warp = (blockIdx.x * blockDim.x + threadIdx.x) >> 5;
    int lane = threadIdx.x & 31;
    if (warp >= NK) return;
    float2 v = reinterpret_cast<const float2*>(W)[(size_t)warp * 32 + lane];
    float ss = v.x * v.x + v.y * v.y;
    #pragma unroll
    for (int off = 16; off > 0; off >>= 1)
        ss += __shfl_xor_sync(0xffffffffu, ss, off);
    if (lane == 0) g_w2[warp] = ss;
}

// ------------------------- kernel 3: argmin (f32x2 SGEMM-argmin) -----------
// Block: 256 threads = 16(tx over k) x 16(ty over q). Micro-tile 8q x 8k.
// NO duplication anywhere: Z stored as natural packed q-pairs, W as natural
// packed k-pairs (32 B/lane/d each). Each 2q x 2k tile = 2 FFMA2:
//   accD += a      * b   -> (qe*ke, qo*ko)
//   accA += swap(a)* b   -> (qo*ke, qe*ko)
// swap is 2 PRMT on the (otherwise idle) ALU pipe.
__global__ __launch_bounds__(256, 2)
void k_argmin(const float* __restrict__ W) {
    extern __shared__ float sm[];
    float* sZ  = sm;                      // 64 * 128 floats (natural q-major-in-d rows)
    float* sW  = sm + 64 * 128;           // 64 * 128 floats
    float* sw2 = sW + 64 * 128;           // 128 floats

    const int tid = threadIdx.x;
    const int tx = tid & 15;
    const int ty = tid >> 4;
    const int q0 = blockIdx.x * TQ;

    // Load Z tile transposed: sZ[d][q] = zn[q0+q][d]
    {
        const float4* Z4 = reinterpret_cast<const float4*>(g_zn) + (size_t)q0 * 16;
        #pragma unroll
        for (int rep = 0; rep < 8; ++rep) {
            int idx = rep * 256 + tid;
            int c4 = idx >> 7, q = idx & 127;
            float4 v = Z4[(size_t)q * 16 + c4];
            sZ[(c4 * 4 + 0) * 128 + q] = v.x;
            sZ[(c4 * 4 + 1) * 128 + q] = v.y;
            sZ[(c4 * 4 + 2) * 128 + q] = v.z;
            sZ[(c4 * 4 + 3) * 128 + q] = v.w;
        }
    }

    // local q slot r -> global q = q0 + ty*8 + r
    float minv[8];
    int   mini[8];
    #pragma unroll
    for (int i = 0; i < 8; ++i) { minv[i] = CUDART_INF_F; mini[i] = 0; }

    for (int kt = 0; kt < NK / TK; ++kt) {
        __syncthreads();  // previous tile compute done (and sZ visible on kt==0)
        // Load W tile transposed: sW[d][k] = W[kt*128+k][d]
        {
            const float4* W4 = reinterpret_cast<const float4*>(W) + (size_t)kt * TK * 16;
            #pragma unroll
            for (int rep = 0; rep < 8; ++rep) {
                int idx = rep * 256 + tid;
                int c4 = idx >> 7, k = idx & 127;
                float4 v = W4[(size_t)k * 16 + c4];
                sW[(c4 * 4 + 0) * 128 + k] = v.x;
                sW[(c4 * 4 + 1) * 128 + k] = v.y;
                sW[(c4 * 4 + 2) * 128 + k] = v.z;
                sW[(c4 * 4 + 3) * 128 + k] = v.w;
            }
            if (tid < 128) sw2[tid] = g_w2[kt * 128 + tid];
        }
        __syncthreads();

        ull accD[16], accA[16];
        #pragma unroll
        for (int i = 0; i < 16; ++i) { accD[i] = 0ull; accA[i] = 0ull; }

        #pragma unroll 8
        for (int d = 0; d < 64; ++d) {
            // B: codes tx*8 + {0..7} as 4 natural pairs -> 2 x LDS.128
            const ull* bp = reinterpret_cast<const ull*>(&sW[d * 128]) + tx * 4;
            ull b0 = bp[0], b1 = bp[1], b2 = bp[2], b3 = bp[3];
            // A: queries ty*8 + {0..7} as 4 natural pairs -> 2 x LDS.128
            const ull* ap = reinterpret_cast<const ull*>(&sZ[d * 128]) + ty * 4;
            ull a0 = ap[0], a1 = ap[1], a2 = ap[2], a3 = ap[3];
            ull s0 = swap2(a0), s1 = swap2(a1), s2 = swap2(a2), s3 = swap2(a3);

            #define QK(qi, A, S)                        \
                fma2(accD[(qi)*4 + 0], (A), b0);        \
                fma2(accA[(qi)*4 + 0], (S), b0);        \
                fma2(accD[(qi)*4 + 1], (A), b1);        \
                fma2(accA[(qi)*4 + 1], (S), b1);        \
                fma2(accD[(qi)*4 + 2], (A), b2);        \
                fma2(accA[(qi)*4 + 2], (S), b2);        \
                fma2(accD[(qi)*4 + 3], (A), b3);        \
                fma2(accA[(qi)*4 + 3], (S), b3);
            QK(0, a0, s0)
            QK(1, a1, s1)
            QK(2, a2, s2)
            QK(3, a3, s3)
            #undef QK
        }

        // epilogue. accD=(qe*ke,qo*ko), accA=(qo*ke,qe*ko).
        // kj ascending, ke before ko, strict < : lowest index wins ties.
        int kbase = kt * 128 + tx * 8;
        #pragma unroll
        for (int qi = 0; qi < 4; ++qi) {
            #pragma unroll
            for (int kj = 0; kj < 4; ++kj) {
                float de, dh, ae, ah;
                unpack2(accD[qi * 4 + kj], de, dh);
                unpack2(accA[qi * 4 + kj], ae, ah);
                float w2e = sw2[tx * 8 + kj * 2];
                float w2o = sw2[tx * 8 + kj * 2 + 1];
                int ke = kbase + kj * 2;
                // q_even (slot 2qi):  (ke: de) (ko: ah)
                float se0 = fmaf(-2.0f, de, w2e);
                float se1 = fmaf(-2.0f, ah, w2o);
                if (se0 < minv[qi * 2]) { minv[qi * 2] = se0; mini[qi * 2] = ke; }
                if (se1 < minv[qi * 2]) { minv[qi * 2] = se1; mini[qi * 2] = ke + 1; }
                // q_odd (slot 2qi+1): (ke: ae) (ko: dh)
                float so0 = fmaf(-2.0f, ae, w2e);
                float so1 = fmaf(-2.0f, dh, w2o);
                if (so0 < minv[qi * 2 + 1]) { minv[qi * 2 + 1] = so0; mini[qi * 2 + 1] = ke; }
                if (so1 < minv[qi * 2 + 1]) { minv[qi * 2 + 1] = so1; mini[qi * 2 + 1] = ke + 1; }
            }
        }
    }

    // reduce across the 16 tx-threads (same half-warp, width 16)
    #pragma unroll
    for (int off = 8; off > 0; off >>= 1) {
        #pragma unroll
        for (int r = 0; r < 8; ++r) {
            float ov = __shfl_down_sync(0xffffffffu, minv[r], off, 16);
            int   oi = __shfl_down_sync(0xffffffffu, mini[r], off, 16);
            if (ov < minv[r] || (ov == minv[r] && oi < mini[r])) {
                minv[r] = ov; mini[r] = oi;
            }
        }
    }
    if (tx == 0) {
        #pragma unroll
        for (int r = 0; r < 8; ++r)
            g_enc[q0 + ty * 8 + r] = mini[r];
    }
}

// ------------------------- kernel 4: scatter / z_q / loss ------------------
__global__ void k_scatter(const float* __restrict__ W, float* __restrict__ out) {
    int warp = (blockIdx.x * blockDim.x + threadIdx.x) >> 5;
    int lane = threadIdx.x & 31;
    if (warp >= NQ) return;
    int e = g_enc[warp];

    float2 wv = reinterpret_cast<const float2*>(W)[(size_t)e * 32 + lane];
    float2 zv = reinterpret_cast<const float2*>(g_zn)[(size_t)warp * 32 + lane];
    float d0 = wv.x - zv.x, d1 = wv.y - zv.y;
    reinterpret_cast<float2*>(out + ZQ_OFF)[(size_t)warp * 32 + lane] =
        make_float2(zv.x + d0, zv.y + d1);

    atomicAdd(&g_es[(size_t)e * 64 + 2 * lane],     zv.x);
    atomicAdd(&g_es[(size_t)e * 64 + 2 * lane + 1], zv.y);

    float part = d0 * d0 + d1 * d1;
    #pragma unroll
    for (int off = 16; off > 0; off >>= 1)
        part += __shfl_xor_sync(0xffffffffu, part, off);
    if (lane == 0) {
        atomicAdd(&g_bins[e], 1.0f);
        atomicAdd(&g_loss, (double)part);
        out[ENC_OFF + warp] = (float)e;
    }
}

// ------------------------- kernel 5: per-code EMA updates ------------------
__global__ void k_update(const float* __restrict__ W,
                         const float* __restrict__ CS,
                         const float* __restrict__ EA,
                         float* __restrict__ out) {
    int warp = (blockIdx.x * blockDim.x + threadIdx.x) >> 5;
    int lane = threadIdx.x & 31;
    if (blockIdx.x == 0 && threadIdx.x == 0) {
        out[LOSS_OFF] = (float)(0.25 * (g_loss / (double)((size_t)NQ * DIM)));
    }
    if (warp >= NK) return;
    int k = warp;

    float b = g_bins[k];
    float2 es = reinterpret_cast<const float2*>(g_es)[(size_t)k * 32 + lane];
    float2 ea = reinterpret_cast<const float2*>(EA)[(size_t)k * 32 + lane];

    out[EA_OFF + (size_t)k * 64 + 2 * lane]     = ea.x * 0.99f + 0.01f * es.x;
    out[EA_OFF + (size_t)k * 64 + 2 * lane + 1] = ea.y * 0.99f + 0.01f * es.y;

    float bc = (b == 0.0f) ? 1.0f : b;
    float vx = es.x / bc, vy = es.y / bc;
    float ss = vx * vx + vy * vy;
    #pragma unroll
    for (int off = 16; off > 0; off >>= 1)
        ss += __shfl_xor_sync(0xffffffffu, ss, off);
    float inv = 1.0f / fmaxf(sqrtf(ss), 1e-12f);

    float2 wv = reinterpret_cast<const float2*>(W)[(size_t)k * 32 + lane];
    float enx = (b == 0.0f) ? wv.x : vx * inv;
    float eny = (b == 0.0f) ? wv.y : vy * inv;

    float nwx = wv.x * 0.99f + 0.01f * enx;
    float nwy = wv.y * 0.99f + 0.01f * eny;
    float ss2 = nwx * nwx + nwy * nwy;
    #pragma unroll
    for (int off = 16; off > 0; off >>= 1)
        ss2 += __shfl_xor_sync(0xffffffffu, ss2, off);
    float inv2 = 1.0f / fmaxf(sqrtf(ss2), 1e-12f);

    out[W_OFF + (size_t)k * 64 + 2 * lane]     = nwx * inv2;
    out[W_OFF + (size_t)k * 64 + 2 * lane + 1] = nwy * inv2;

    if (lane == 0) out[CS_OFF + k] = CS[k] * 0.99f + 0.01f * b;
}

// ------------------------- launch -------------------------------------------
extern "C" void kernel_launch(void* const* d_in, const int* in_sizes, int n_in,
                              void* d_out, int out_size) {
    const float* z  = (const float*)d_in[0];
    const float* w  = (const float*)d_in[1];
    const float* cs = (const float*)d_in[2];
    const float* ea = (const float*)d_in[3];
    float* out = (float*)d_out;

    const int smem_bytes = (2 * 64 * 128 + 128) * sizeof(float);  // 66048
    cudaFuncSetAttribute(k_argmin, cudaFuncAttributeMaxDynamicSharedMemorySize,
                         smem_bytes);

    k_zero<<<(NK * DIM + NK + 255) / 256, 256>>>();
    k_normz<<<NQ / 8, 256>>>(z);
    k_w2<<<NK / 8, 256>>>(w);
    k_argmin<<<NQ / TQ, 256, smem_bytes>>>(w);
    k_scatter<<<NQ / 8, 256>>>(w, out);
    k_update<<<NK / 8, 256>>>(w, cs, ea, out);
}